// round 15
// baseline (speedup 1.0000x reference)
#include <cuda_runtime.h>
#include <cstdint>
#include <math.h>

#define B_ 128
#define T_ 100
#define E_ 128
#define F_ 700
#define S_ 400
#define V_ 10000

#define NCTA 592           // 148 SMs x 4 CTAs, residency-guaranteed
#define PTH 128            // threads per persistent CTA

// ---------------- static device scratch (no allocations allowed) ----------------
static __device__ __align__(16) float g_fh[B_ * F_];
static __device__ __align__(16) float g_fc[B_ * F_];
static __device__ __align__(16) float g_sh[B_ * S_];
static __device__ __align__(16) float g_sc[B_ * S_];
// split-K partial planes: fast 4 * 128*2800 = slow 7 * 128*1600 = 1,433,600 floats (5.7 MB)
static __device__ __align__(16) float g_z[4 * B_ * 4 * F_];
static __device__ __align__(16) float g_outs[B_ * T_ * F_];   // fh outputs, row = b*T + t
static __device__ unsigned g_bar_count = 0;
static __device__ unsigned g_bar_gen = 0;

// ---------------- helpers ----------------
__device__ __forceinline__ uint32_t f2tf32(float x) {
    uint32_t r;
    asm("cvt.rna.tf32.f32 %0, %1;" : "=r"(r) : "f"(x));
    return r;
}
__device__ __forceinline__ void f2tf32_split(float x, uint32_t& hi, uint32_t& lo) {
    hi = f2tf32(x);
    lo = f2tf32(x - __uint_as_float(hi));
}
__device__ __forceinline__ void mma_tf32(float* d, const uint32_t* a, const uint32_t* b) {
    asm volatile(
        "mma.sync.aligned.m16n8k8.row.col.f32.tf32.tf32.f32 "
        "{%0,%1,%2,%3}, {%4,%5,%6,%7}, {%8,%9}, {%0,%1,%2,%3};\n"
        : "+f"(d[0]), "+f"(d[1]), "+f"(d[2]), "+f"(d[3])
        : "r"(a[0]), "r"(a[1]), "r"(a[2]), "r"(a[3]), "r"(b[0]), "r"(b[1]));
}
__device__ __forceinline__ void cp16(void* smem, const void* gmem, int szbytes) {
    uint32_t s = (uint32_t)__cvta_generic_to_shared(smem);
    asm volatile("cp.async.cg.shared.global [%0], [%1], 16, %2;\n"
                 :: "r"(s), "l"(gmem), "r"(szbytes));
}
__device__ __forceinline__ void cp_commit() { asm volatile("cp.async.commit_group;\n"); }
template <int N> __device__ __forceinline__ void cp_wait() {
    asm volatile("cp.async.wait_group %0;\n" :: "n"(N));
}
__device__ __forceinline__ float sigm(float x) { return 1.0f / (1.0f + expf(-x)); }

// ---------------- software grid barrier (all NCTA CTAs resident by construction) ----------
__device__ __forceinline__ void grid_sync() {
    __syncthreads();
    if (threadIdx.x == 0) {
        __threadfence();
        unsigned gen = *(volatile unsigned*)&g_bar_gen;
        unsigned ticket = atomicAdd(&g_bar_count, 1u);
        if (ticket == NCTA - 1) {
            g_bar_count = 0;
            __threadfence();
            *(volatile unsigned*)&g_bar_gen = gen + 1;
        } else {
            while (*(volatile unsigned*)&g_bar_gen == gen) __nanosleep(64);
        }
    }
    __syncthreads();
}

// ---------------- persistent-phase GEMM (3xTF32 + fp64 acc, 2-stage cp.async) -------------
// BM=64, BN=32, 4 warps (2x2). Tasks = xTiles * 2 * NSPLIT, strided over NCTA CTAs.
// smem layout in smraw: As[2][64][36] @0 (18432B), Bs[2][32][40] @18432 (10240B).
template <int NSPLIT>
__device__ void gemm_phase(const float* __restrict__ A1, int lda1, int K1,
                           const float* __restrict__ A2, int lda2,
                           const float* __restrict__ W,
                           float* __restrict__ C, int N, int K, size_t pstride,
                           int xTiles, char* smraw) {
    constexpr int BK = 32, BM = 64, BN = 32;
    constexpr int AST = 36, BST = 40;
    float (*As)[BM][AST] = (float(*)[BM][AST])smraw;
    float (*Bs)[BK][BST] = (float(*)[BK][BST])(smraw + 2 * BM * AST * 4);

    const int tid  = threadIdx.x;
    const int wid  = tid >> 5;
    const int lane = tid & 31;
    const int g    = lane >> 2;
    const int tq   = lane & 3;
    const int warp_m = wid & 1;
    const int warp_n = wid >> 1;
    const int nblk = (K + BK - 1) / BK;
    const int nTasks = xTiles * 2 * NSPLIT;

    for (int task = blockIdx.x; task < nTasks; task += NCTA) {
        const int x   = task % xTiles;
        const int rem = task / xTiles;
        const int y   = rem & 1;
        const int zb  = rem >> 1;
        const int m0 = y * BM, n0 = x * BN;
        const int kBegin = ((zb * nblk) / NSPLIT) * BK;
        const int kEnd   = (zb == NSPLIT - 1) ? K : (((zb + 1) * nblk) / NSPLIT) * BK;
        float* Cz = C + (size_t)zb * pstride;

        double acc[2][2][4];
#pragma unroll
        for (int mf = 0; mf < 2; ++mf)
#pragma unroll
            for (int nf = 0; nf < 2; ++nf)
#pragma unroll
                for (int r = 0; r < 4; ++r) acc[mf][nf][r] = 0.0;

        auto load_tiles = [&](int k0, int s) {
#pragma unroll
            for (int i = 0; i < 4; ++i) {              // 64x32 floats / 128 thr / 4-wide
                int p   = tid + i * PTH;
                int row = p >> 3;
                int kc  = (p & 7) << 2;
                int k   = k0 + kc;
                const float* src = A1;
                int sz = 0;
                if (k < K) {
                    int gr = m0 + row;
                    sz = 16;
                    if (k + 4 <= K1) src = A1 + (size_t)gr * lda1 + k;
                    else             src = A2 + (size_t)gr * lda2 + (k - K1);
                }
                cp16(&As[s][row][kc], src, sz);
            }
#pragma unroll
            for (int i = 0; i < 2; ++i) {              // 32x32 floats / 128 thr / 4-wide
                int p  = tid + i * PTH;
                int kr = p >> 3;
                int nc = (p & 7) << 2;
                int n  = n0 + nc;
                int k  = k0 + kr;
                const float* src = W;
                int sz = 0;
                if (k < K && n < N) { sz = 16; src = W + (size_t)k * N + n; }
                cp16(&Bs[s][kr][nc], src, sz);
            }
        };

        auto compute = [&](int s) {
            float pac[2][2][4];
#pragma unroll
            for (int mf = 0; mf < 2; ++mf)
#pragma unroll
                for (int nf = 0; nf < 2; ++nf)
#pragma unroll
                    for (int r = 0; r < 4; ++r) pac[mf][nf][r] = 0.0f;
#pragma unroll
            for (int kk = 0; kk < 4; ++kk) {
                uint32_t afh[2][4], afl[2][4], bfh[2][2], bfl[2][2];
#pragma unroll
                for (int mf = 0; mf < 2; ++mf) {
                    int r = warp_m * 32 + mf * 16;
                    f2tf32_split(As[s][r + g][kk * 8 + tq],         afh[mf][0], afl[mf][0]);
                    f2tf32_split(As[s][r + g + 8][kk * 8 + tq],     afh[mf][1], afl[mf][1]);
                    f2tf32_split(As[s][r + g][kk * 8 + tq + 4],     afh[mf][2], afl[mf][2]);
                    f2tf32_split(As[s][r + g + 8][kk * 8 + tq + 4], afh[mf][3], afl[mf][3]);
                }
#pragma unroll
                for (int nf = 0; nf < 2; ++nf) {
                    int cn = warp_n * 16 + nf * 8 + g;
                    f2tf32_split(Bs[s][kk * 8 + tq][cn],     bfh[nf][0], bfl[nf][0]);
                    f2tf32_split(Bs[s][kk * 8 + tq + 4][cn], bfh[nf][1], bfl[nf][1]);
                }
#pragma unroll
                for (int mf = 0; mf < 2; ++mf)
#pragma unroll
                    for (int nf = 0; nf < 2; ++nf) {
                        mma_tf32(pac[mf][nf], afl[mf], bfh[nf]);
                        mma_tf32(pac[mf][nf], afh[mf], bfl[nf]);
                        mma_tf32(pac[mf][nf], afh[mf], bfh[nf]);
                    }
            }
#pragma unroll
            for (int mf = 0; mf < 2; ++mf)
#pragma unroll
                for (int nf = 0; nf < 2; ++nf)
#pragma unroll
                    for (int r = 0; r < 4; ++r) acc[mf][nf][r] += (double)pac[mf][nf][r];
        };

        load_tiles(kBegin, 0);
        cp_commit();
        int buf = 0;
        for (int k0 = kBegin; k0 < kEnd; k0 += BK) {
            if (k0 + BK < kEnd) load_tiles(k0 + BK, buf ^ 1);
            cp_commit();
            cp_wait<1>();
            __syncthreads();
            compute(buf);
            __syncthreads();
            buf ^= 1;
        }

#pragma unroll
        for (int mf = 0; mf < 2; ++mf)
#pragma unroll
            for (int nf = 0; nf < 2; ++nf) {
                int row = m0 + warp_m * 32 + mf * 16 + g;
                int col = n0 + warp_n * 16 + nf * 8 + tq * 2;
                if (col < N) {
                    float2 v0 = make_float2((float)acc[mf][nf][0], (float)acc[mf][nf][1]);
                    float2 v1 = make_float2((float)acc[mf][nf][2], (float)acc[mf][nf][3]);
                    *(float2*)(Cz + (size_t)row * N + col)       = v0;
                    *(float2*)(Cz + (size_t)(row + 8) * N + col) = v1;
                }
            }
    }
}

// ---------------- persistent-phase pointwise (CTA b < B_ handles row b) -------------------
// smem in smraw: sz float[4*HU] @0, scp float[HU] @4*HU*4, redd double[16] @28480, stat @28608
template <int HU, int NS>
__device__ void pw_phase(const float* __restrict__ z, size_t pstride,
                         const float* __restrict__ bias,
                         const float* __restrict__ gg, const float* __restrict__ bg,
                         const float* __restrict__ gc, const float* __restrict__ bc,
                         float* __restrict__ h, float* __restrict__ c,
                         float* __restrict__ outs, char* smraw) {
    if (blockIdx.x >= B_) return;
    float*  sz   = (float*)smraw;
    float*  scp  = (float*)(smraw + 4 * HU * 4);
    double* redd = (double*)(smraw + 28480);
    float*  stat = (float*)(smraw + 28608);

    const int b = blockIdx.x, tid = threadIdx.x;
    const float* zr = z + (size_t)b * 4 * HU;

    for (int i = tid; i < 4 * HU; i += PTH) {
        float v = __ldcg(&zr[i]);                    // L2 read: written by GEMM CTAs
#pragma unroll
        for (int s = 1; s < NS; ++s) v += __ldcg(&zr[s * pstride + i]);
        sz[i] = v + bias[i];
    }
    __syncthreads();

    for (int ch = 0; ch < 4; ++ch) {
        double s = 0.0, q = 0.0;
        for (int i = tid; i < HU; i += PTH) {
            double v = (double)sz[ch * HU + i];
            s += v; q += v * v;
        }
#pragma unroll
        for (int o = 16; o; o >>= 1) { s += __shfl_xor_sync(~0u, s, o); q += __shfl_xor_sync(~0u, q, o); }
        if ((tid & 31) == 0) { redd[tid >> 5] = s; redd[8 + (tid >> 5)] = q; }
        __syncthreads();
        if (tid < 32) {
            double ss = (tid < 4) ? redd[tid] : 0.0;
            double qq = (tid < 4) ? redd[8 + tid] : 0.0;
#pragma unroll
            for (int o = 2; o; o >>= 1) { ss += __shfl_xor_sync(~0u, ss, o); qq += __shfl_xor_sync(~0u, qq, o); }
            if (tid == 0) {
                double mu = ss / (double)HU;
                double var = qq / (double)HU - mu * mu;
                stat[ch] = (float)mu;
                stat[4 + ch] = (float)(1.0 / sqrt(var + 1e-5));
            }
        }
        __syncthreads();
    }

    const float mu0 = stat[0], mu1 = stat[1], mu2 = stat[2], mu3 = stat[3];
    const float r0 = stat[4], r1 = stat[5], r2 = stat[6], r3 = stat[7];

    for (int i = tid; i < HU; i += PTH) {
        float iv = (sz[i]          - mu0) * r0 * gg[i]          + bg[i];
        float jv = (sz[HU + i]     - mu1) * r1 * gg[HU + i]     + bg[HU + i];
        float fv = (sz[2 * HU + i] - mu2) * r2 * gg[2 * HU + i] + bg[2 * HU + i];
        float ov = (sz[3 * HU + i] - mu3) * r3 * gg[3 * HU + i] + bg[3 * HU + i];
        float cold = c[(size_t)b * HU + i];
        float cpre = cold * sigm(fv + 1.0f) + sigm(iv) * tanhf(jv);
        scp[i] = cpre;
        sz[3 * HU + i] = ov;
    }
    __syncthreads();

    {
        double s = 0.0, q = 0.0;
        for (int i = tid; i < HU; i += PTH) {
            double v = (double)scp[i];
            s += v; q += v * v;
        }
#pragma unroll
        for (int o = 16; o; o >>= 1) { s += __shfl_xor_sync(~0u, s, o); q += __shfl_xor_sync(~0u, q, o); }
        if ((tid & 31) == 0) { redd[tid >> 5] = s; redd[8 + (tid >> 5)] = q; }
        __syncthreads();
        if (tid < 32) {
            double ss = (tid < 4) ? redd[tid] : 0.0;
            double qq = (tid < 4) ? redd[8 + tid] : 0.0;
#pragma unroll
            for (int o = 2; o; o >>= 1) { ss += __shfl_xor_sync(~0u, ss, o); qq += __shfl_xor_sync(~0u, qq, o); }
            if (tid == 0) {
                double mu = ss / (double)HU;
                double var = qq / (double)HU - mu * mu;
                stat[8] = (float)mu;
                stat[9] = (float)(1.0 / sqrt(var + 1e-5));
            }
        }
        __syncthreads();
    }
    const float muc = stat[8], rc = stat[9];

    for (int i = tid; i < HU; i += PTH) {
        float cpre = scp[i];
        float nh = tanhf((cpre - muc) * rc * gc[i] + bc[i]) * sigm(sz[3 * HU + i]);
        float hold = h[(size_t)b * HU + i];
        float cold = c[(size_t)b * HU + i];
        float hn = 0.9f * nh + 0.1f * hold;
        float cn = 0.5f * cpre + 0.5f * cold;
        h[(size_t)b * HU + i] = hn;
        c[(size_t)b * HU + i] = cn;
        if (outs) outs[(size_t)b * T_ * HU + i] = hn;
    }
    __syncthreads();   // protect smem reuse by next phase (same CTA)
}

// ---------------- THE persistent recurrence kernel ----------------------------------------
__global__ void __launch_bounds__(PTH, 4)
recurrence_kernel(const float* __restrict__ inputs,
                  const float* __restrict__ W0, const float* __restrict__ b0,
                  const float* __restrict__ g0, const float* __restrict__ bg0,
                  const float* __restrict__ gc0, const float* __restrict__ bc0,
                  const float* __restrict__ W1, const float* __restrict__ b1,
                  const float* __restrict__ g1, const float* __restrict__ bg1,
                  const float* __restrict__ gc1, const float* __restrict__ bc1,
                  const float* __restrict__ WS, const float* __restrict__ bS,
                  const float* __restrict__ gS, const float* __restrict__ bgS,
                  const float* __restrict__ gcS, const float* __restrict__ bcS) {
    static __shared__ __align__(16) char smraw[28672];
    const size_t psF = (size_t)B_ * 4 * F_;
    const size_t psS = (size_t)B_ * 4 * S_;

    // zero phase: CTA b zeroes ITS OWN state rows (keeps h/c strictly CTA-private)
    if (blockIdx.x < B_) {
        int b = blockIdx.x;
        for (int i = threadIdx.x; i < F_; i += PTH) { g_fh[b * F_ + i] = 0.f; g_fc[b * F_ + i] = 0.f; }
        for (int i = threadIdx.x; i < S_; i += PTH) { g_sh[b * S_ + i] = 0.f; g_sc[b * S_ + i] = 0.f; }
    }
    grid_sync();

    for (int t = 0; t < T_; ++t) {
        gemm_phase<4>(inputs + (size_t)t * E_, T_ * E_, E_, g_fh, F_, W0,
                      g_z, 4 * F_, E_ + F_, psF, 88, smraw);
        grid_sync();
        pw_phase<F_, 4>(g_z, psF, b0, g0, bg0, gc0, bc0, g_fh, g_fc, nullptr, smraw);
        grid_sync();

        gemm_phase<7>(g_fh, F_, F_, g_sh, S_, WS,
                      g_z, 4 * S_, F_ + S_, psS, 50, smraw);
        grid_sync();
        pw_phase<S_, 7>(g_z, psS, bS, gS, bgS, gcS, bcS, g_sh, g_sc, nullptr, smraw);
        grid_sync();

        gemm_phase<4>(g_sh, S_, S_, g_fh, F_, W1,
                      g_z, 4 * F_, S_ + F_, psF, 88, smraw);
        grid_sync();
        pw_phase<F_, 4>(g_z, psF, b1, g1, bg1, gc1, bc1, g_fh, g_fc,
                        g_outs + (size_t)t * F_, smraw);
        grid_sync();
    }
}

// ---------------- output GEMM (unchanged single-TF32 path) --------------------------------
template <int BM, int BN, int WM_, int WN_>
__global__ void __launch_bounds__(WM_ * WN_ * 32)
gemm_out_kernel(const float* __restrict__ A, int lda,
                const float* __restrict__ W, const float* __restrict__ bias,
                float* __restrict__ C, int N, int K) {
    constexpr int BK = 32;
    constexpr int NTH = WM_ * WN_ * 32;
    constexpr int WTM = BM / WM_;
    constexpr int WTN = BN / WN_;
    constexpr int MF = WTM / 16;
    constexpr int NF = WTN / 8;
    constexpr int AST = BK + 4;
    constexpr int BST = BN + 8;

    __shared__ float As[BM][AST];
    __shared__ float Bs[BK][BST];

    const int tid  = threadIdx.x;
    const int wid  = tid >> 5;
    const int lane = tid & 31;
    const int g    = lane >> 2;
    const int tq   = lane & 3;
    const int warp_m = wid % WM_;
    const int warp_n = wid / WM_;
    const int m0 = blockIdx.y * BM;
    const int n0 = blockIdx.x * BN;

    float acc[MF][NF][4];
#pragma unroll
    for (int mf = 0; mf < MF; ++mf)
#pragma unroll
        for (int nf = 0; nf < NF; ++nf)
#pragma unroll
            for (int r = 0; r < 4; ++r) acc[mf][nf][r] = 0.0f;

    for (int k0 = 0; k0 < K; k0 += BK) {
        constexpr int AF4 = BM * BK / 4;
#pragma unroll
        for (int i = 0; i < AF4 / NTH; ++i) {
            int p   = tid + i * NTH;
            int row = p >> 3;
            int kc  = (p & 7) << 2;
            int k   = k0 + kc;
            const float* src = A;
            int sz = 0;
            if (k < K) { sz = 16; src = A + (size_t)(m0 + row) * lda + k; }
            cp16(&As[row][kc], src, sz);
        }
        constexpr int BF4 = BK * BN / 4;
#pragma unroll
        for (int i = 0; i < BF4 / NTH; ++i) {
            int p  = tid + i * NTH;
            int kr = p / (BN / 4);
            int nc = (p % (BN / 4)) << 2;
            int n  = n0 + nc;
            int k  = k0 + kr;
            const float* src = W;
            int sz = 0;
            if (k < K && n < N) { sz = 16; src = W + (size_t)k * N + n; }
            cp16(&Bs[kr][nc], src, sz);
        }
        cp_commit();
        cp_wait<0>();
        __syncthreads();

#pragma unroll
        for (int kk = 0; kk < 4; ++kk) {
            uint32_t af[MF][4], bf[NF][2];
#pragma unroll
            for (int mf = 0; mf < MF; ++mf) {
                int r = warp_m * WTM + mf * 16;
                af[mf][0] = f2tf32(As[r + g][kk * 8 + tq]);
                af[mf][1] = f2tf32(As[r + g + 8][kk * 8 + tq]);
                af[mf][2] = f2tf32(As[r + g][kk * 8 + tq + 4]);
                af[mf][3] = f2tf32(As[r + g + 8][kk * 8 + tq + 4]);
            }
#pragma unroll
            for (int nf = 0; nf < NF; ++nf) {
                int cn = warp_n * WTN + nf * 8 + g;
                bf[nf][0] = f2tf32(Bs[kk * 8 + tq][cn]);
                bf[nf][1] = f2tf32(Bs[kk * 8 + tq + 4][cn]);
            }
#pragma unroll
            for (int mf = 0; mf < MF; ++mf)
#pragma unroll
                for (int nf = 0; nf < NF; ++nf) mma_tf32(acc[mf][nf], af[mf], bf[nf]);
        }
        __syncthreads();
    }

#pragma unroll
    for (int mf = 0; mf < MF; ++mf) {
#pragma unroll
        for (int nf = 0; nf < NF; ++nf) {
            int row = m0 + warp_m * WTM + mf * 16 + g;
            int col = n0 + warp_n * WTN + nf * 8 + tq * 2;
            if (col < N) {
                float bx = bias[col], by = bias[col + 1];
                float2 v0 = make_float2(acc[mf][nf][0] + bx, acc[mf][nf][1] + by);
                float2 v1 = make_float2(acc[mf][nf][2] + bx, acc[mf][nf][3] + by);
                *(float2*)(C + (size_t)row * N + col)       = v0;
                *(float2*)(C + (size_t)(row + 8) * N + col) = v1;
            }
        }
    }
}

// ---------------- epilogue ----------------
__global__ void copy_states_kernel(float* __restrict__ out) {
    int i = blockIdx.x * blockDim.x + threadIdx.x;
    const int NF = B_ * F_;
    const int NS = B_ * S_;
    if (i < NF)                       out[i] = g_fh[i];
    else if (i < 2 * NF)              out[i] = g_fc[i - NF];
    else if (i < 2 * NF + NS)         out[i] = g_sh[i - 2 * NF];
    else if (i < 2 * NF + 2 * NS)     out[i] = g_sc[i - 2 * NF - NS];
}

// ---------------- launch ----------------
extern "C" void kernel_launch(void* const* d_in, const int* in_sizes, int n_in,
                              void* d_out, int out_size) {
    const float* inputs = (const float*)d_in[0];
    const float* W0  = (const float*)d_in[1];
    const float* b0  = (const float*)d_in[2];
    const float* g0  = (const float*)d_in[3];
    const float* bg0 = (const float*)d_in[4];
    const float* gc0 = (const float*)d_in[5];
    const float* bc0 = (const float*)d_in[6];
    const float* W1  = (const float*)d_in[7];
    const float* b1  = (const float*)d_in[8];
    const float* g1  = (const float*)d_in[9];
    const float* bg1 = (const float*)d_in[10];
    const float* gc1 = (const float*)d_in[11];
    const float* bc1 = (const float*)d_in[12];
    const float* WS  = (const float*)d_in[13];
    const float* bS  = (const float*)d_in[14];
    const float* gS  = (const float*)d_in[15];
    const float* bgS = (const float*)d_in[16];
    const float* gcS = (const float*)d_in[17];
    const float* bcS = (const float*)d_in[18];
    const float* Wout = (const float*)d_in[19];
    const float* bout = (const float*)d_in[20];
    float* out = (float*)d_out;

    float *outs;
    cudaGetSymbolAddress((void**)&outs, g_outs);

    // whole recurrence in ONE persistent kernel (600 launches -> 1)
    recurrence_kernel<<<NCTA, PTH>>>(inputs,
                                     W0, b0, g0, bg0, gc0, bc0,
                                     W1, b1, g1, bg1, gc1, bc1,
                                     WS, bS, gS, bgS, gcS, bcS);

    // Output projection: g_outs[12800,700] @ Wout[700,10000] + bout -> logits
    gemm_out_kernel<128, 128, 2, 4><<<dim3(79, 100), 256>>>(
        outs, F_, Wout, bout, out, V_, F_);

    // Final states appended after logits
    copy_states_kernel<<<1100, 256>>>(out + (size_t)B_ * T_ * V_);
}

// round 16
// speedup vs baseline: 1.1034x; 1.1034x over previous
#include <cuda_runtime.h>
#include <cstdint>
#include <math.h>

#define B_ 128
#define T_ 100
#define E_ 128
#define F_ 700
#define S_ 400
#define V_ 10000

// ---------------- static device scratch (no allocations allowed) ----------------
static __device__ __align__(16) float g_fh[B_ * F_];
static __device__ __align__(16) float g_fc[B_ * F_];
static __device__ __align__(16) float g_sh[B_ * S_];
static __device__ __align__(16) float g_sc[B_ * S_];
// split-K partial planes: fast 4 * 128*2800 = slow 7 * 128*1600 = 1,433,600 floats (5.7 MB)
static __device__ __align__(16) float g_z[4 * B_ * 4 * F_];
static __device__ __align__(16) float g_outs[B_ * T_ * F_];      // fh outputs, row = b*T + t  (35.8 MB)

// ---------------- helpers ----------------
__device__ __forceinline__ uint32_t f2tf32(float x) {
    uint32_t r;
    asm("cvt.rna.tf32.f32 %0, %1;" : "=r"(r) : "f"(x));
    return r;
}

// split x into hi (tf32) + lo (tf32 of residual): 3xTF32 emulation of fp32
__device__ __forceinline__ void f2tf32_split(float x, uint32_t& hi, uint32_t& lo) {
    hi = f2tf32(x);
    lo = f2tf32(x - __uint_as_float(hi));
}

__device__ __forceinline__ void mma_tf32(float* d, const uint32_t* a, const uint32_t* b) {
    asm volatile(
        "mma.sync.aligned.m16n8k8.row.col.f32.tf32.tf32.f32 "
        "{%0,%1,%2,%3}, {%4,%5,%6,%7}, {%8,%9}, {%0,%1,%2,%3};\n"
        : "+f"(d[0]), "+f"(d[1]), "+f"(d[2]), "+f"(d[3])
        : "r"(a[0]), "r"(a[1]), "r"(a[2]), "r"(a[3]), "r"(b[0]), "r"(b[1]));
}

__device__ __forceinline__ void cp16(void* smem, const void* gmem, int szbytes) {
    uint32_t s = (uint32_t)__cvta_generic_to_shared(smem);
    asm volatile("cp.async.cg.shared.global [%0], [%1], 16, %2;\n"
                 :: "r"(s), "l"(gmem), "r"(szbytes));
}
__device__ __forceinline__ void cp_commit() { asm volatile("cp.async.commit_group;\n"); }
template <int N> __device__ __forceinline__ void cp_wait() {
    asm volatile("cp.async.wait_group %0;\n" :: "n"(N));
}

__device__ __forceinline__ float sigm(float x) { return 1.0f / (1.0f + expf(-x)); }

// accumulator type: fp64 on the recurrent (SPLIT) path to sink accumulation-order noise
template <bool SPLIT> struct AccType { typedef float T; };
template <> struct AccType<true> { typedef double T; };

// ---------------- TF32 GEMM: C[M,N] = concat(A1,A2)[M,K] @ W[K,N] (+bias) ----------------
// Virtual concat A: cols [0,K1) from A1 (row stride lda1), cols [K1,K) from A2 (row stride lda2).
// K1 % 4 == 0, N % 4 == 0, M exact multiple of BM.
// SPLIT=true: 3xTF32 split precision + per-K-block fp32 partials flushed into an fp64
// main accumulator.
// NSPLIT>1: split-K — blockIdx.z covers K-range [kBegin,kEnd) on BK boundaries, writing a
// partial plane at C + z*pstride. Consumer sums planes in fixed order (deterministic).
template <int BM, int BN, int WM_, int WN_, int STAGES, bool SPLIT, int NSPLIT, int MINCTA>
__global__ void __launch_bounds__(WM_ * WN_ * 32, MINCTA)
gemm_tf32_kernel(const float* __restrict__ A1, int lda1, int K1,
                 const float* __restrict__ A2, int lda2,
                 const float* __restrict__ W, const float* __restrict__ bias,
                 float* __restrict__ C, int N, int K, size_t pstride) {
    constexpr int BK = 32;
    constexpr int NTH = WM_ * WN_ * 32;
    constexpr int WTM = BM / WM_;
    constexpr int WTN = BN / WN_;
    constexpr int MF = WTM / 16;
    constexpr int NF = WTN / 8;
    constexpr int AST = BK + 4;        // %32==4 -> conflict-free A frag LDS
    constexpr int BST = BN + 8;        // %32==8 -> conflict-free B frag LDS
    typedef typename AccType<SPLIT>::T accT;

    __shared__ float As[STAGES][BM][AST];
    __shared__ float Bs[STAGES][BK][BST];

    const int tid  = threadIdx.x;
    const int wid  = tid >> 5;
    const int lane = tid & 31;
    const int g    = lane >> 2;
    const int tq   = lane & 3;
    const int warp_m = wid % WM_;
    const int warp_n = wid / WM_;
    const int m0 = blockIdx.y * BM;
    const int n0 = blockIdx.x * BN;

    // ---- split-K range (BK-aligned; last split takes the K tail) ----
    const int nblk = (K + BK - 1) / BK;
    const int zb = (NSPLIT > 1) ? blockIdx.z : 0;
    const int kBegin = ((zb * nblk) / NSPLIT) * BK;
    const int kEnd   = (zb == NSPLIT - 1) ? K : (((zb + 1) * nblk) / NSPLIT) * BK;
    float* Cz = C + (size_t)zb * pstride;

    accT acc[MF][NF][4];
#pragma unroll
    for (int mf = 0; mf < MF; ++mf)
#pragma unroll
        for (int nf = 0; nf < NF; ++nf)
#pragma unroll
            for (int r = 0; r < 4; ++r) acc[mf][nf][r] = (accT)0;

    // ---- async tile loader ----
    auto load_tiles = [&](int k0, int s) {
        constexpr int AF4 = BM * BK / 4;
#pragma unroll
        for (int i = 0; i < AF4 / NTH; ++i) {
            int p   = tid + i * NTH;
            int row = p >> 3;
            int kc  = (p & 7) << 2;
            int k   = k0 + kc;
            const float* src = A1;      // valid aligned dummy when sz==0
            int sz = 0;
            if (k < K) {                // k,K1 %4 -> float4 never straddles
                int gr = m0 + row;
                sz = 16;
                if (k + 4 <= K1) src = A1 + (size_t)gr * lda1 + k;
                else             src = A2 + (size_t)gr * lda2 + (k - K1);
            }
            cp16(&As[s][row][kc], src, sz);
        }
        constexpr int BF4 = BK * BN / 4;
#pragma unroll
        for (int i = 0; i < BF4 / NTH; ++i) {
            int p  = tid + i * NTH;
            int kr = p / (BN / 4);
            int nc = (p % (BN / 4)) << 2;
            int n  = n0 + nc;
            int k  = k0 + kr;
            const float* src = W;
            int sz = 0;
            if (k < K && n < N) { sz = 16; src = W + (size_t)k * N + n; }
            cp16(&Bs[s][kr][nc], src, sz);
        }
    };

    // compute one K-block into a zeroed fp32 partial accumulator, then flush to main acc
    auto compute = [&](int s) {
        float pac[MF][NF][4];
#pragma unroll
        for (int mf = 0; mf < MF; ++mf)
#pragma unroll
            for (int nf = 0; nf < NF; ++nf)
#pragma unroll
                for (int r = 0; r < 4; ++r) pac[mf][nf][r] = 0.0f;

#pragma unroll
        for (int kk = 0; kk < 4; ++kk) {
            uint32_t afh[MF][4], bfh[NF][2];
            uint32_t afl[MF][4], bfl[NF][2];
#pragma unroll
            for (int mf = 0; mf < MF; ++mf) {
                int r = warp_m * WTM + mf * 16;
                float a0 = As[s][r + g][kk * 8 + tq];
                float a1 = As[s][r + g + 8][kk * 8 + tq];
                float a2 = As[s][r + g][kk * 8 + tq + 4];
                float a3 = As[s][r + g + 8][kk * 8 + tq + 4];
                if (SPLIT) {
                    f2tf32_split(a0, afh[mf][0], afl[mf][0]);
                    f2tf32_split(a1, afh[mf][1], afl[mf][1]);
                    f2tf32_split(a2, afh[mf][2], afl[mf][2]);
                    f2tf32_split(a3, afh[mf][3], afl[mf][3]);
                } else {
                    afh[mf][0] = f2tf32(a0); afh[mf][1] = f2tf32(a1);
                    afh[mf][2] = f2tf32(a2); afh[mf][3] = f2tf32(a3);
                }
            }
#pragma unroll
            for (int nf = 0; nf < NF; ++nf) {
                int cn = warp_n * WTN + nf * 8 + g;
                float b0 = Bs[s][kk * 8 + tq][cn];
                float b1 = Bs[s][kk * 8 + tq + 4][cn];
                if (SPLIT) {
                    f2tf32_split(b0, bfh[nf][0], bfl[nf][0]);
                    f2tf32_split(b1, bfh[nf][1], bfl[nf][1]);
                } else {
                    bfh[nf][0] = f2tf32(b0); bfh[nf][1] = f2tf32(b1);
                }
            }
#pragma unroll
            for (int mf = 0; mf < MF; ++mf)
#pragma unroll
                for (int nf = 0; nf < NF; ++nf) {
                    if (SPLIT) {
                        // small cross terms first, then hi*hi
                        mma_tf32(pac[mf][nf], afl[mf], bfh[nf]);
                        mma_tf32(pac[mf][nf], afh[mf], bfl[nf]);
                    }
                    mma_tf32(pac[mf][nf], afh[mf], bfh[nf]);
                }
        }
        // flush block partial into main accumulator (fp64 add on SPLIT path)
#pragma unroll
        for (int mf = 0; mf < MF; ++mf)
#pragma unroll
            for (int nf = 0; nf < NF; ++nf)
#pragma unroll
                for (int r = 0; r < 4; ++r) acc[mf][nf][r] += (accT)pac[mf][nf][r];
    };

    if (STAGES == 2) {
        load_tiles(kBegin, 0);
        cp_commit();
        int buf = 0;
        for (int k0 = kBegin; k0 < kEnd; k0 += BK) {
            if (k0 + BK < kEnd) load_tiles(k0 + BK, buf ^ 1);
            cp_commit();
            cp_wait<1>();          // current buf's group complete
            __syncthreads();
            compute(buf);
            __syncthreads();
            buf ^= 1;
        }
    } else {
        for (int k0 = kBegin; k0 < kEnd; k0 += BK) {
            load_tiles(k0, 0);
            cp_commit();
            cp_wait<0>();
            __syncthreads();
            compute(0);
            __syncthreads();
        }
    }

    // ---- store (float2; N even, col-tail checked) ----
#pragma unroll
    for (int mf = 0; mf < MF; ++mf) {
#pragma unroll
        for (int nf = 0; nf < NF; ++nf) {
            int row = m0 + warp_m * WTM + mf * 16 + g;
            int col = n0 + warp_n * WTN + nf * 8 + tq * 2;
            if (col < N) {
                float bx = 0.f, by = 0.f;
                if (bias) { bx = bias[col]; by = bias[col + 1]; }
                float2 v0 = make_float2((float)acc[mf][nf][0] + bx, (float)acc[mf][nf][1] + by);
                float2 v1 = make_float2((float)acc[mf][nf][2] + bx, (float)acc[mf][nf][3] + by);
                *(float2*)(Cz + (size_t)row * N + col)       = v0;
                *(float2*)(Cz + (size_t)(row + 8) * N + col) = v1;
            }
        }
    }
}

// ---------------- fused split-K reduce + LN4 + gates + LN(c) + zoneout ----------------
// One CTA per batch row. Sums NS split-K partial planes in fixed order (deterministic),
// LayerNorm statistics in fp64.
template <int HU, int NS>
__global__ void __launch_bounds__(256)
pointwise_kernel(const float* __restrict__ z, size_t pstride,
                 const float* __restrict__ bias,
                 const float* __restrict__ gg, const float* __restrict__ bg,
                 const float* __restrict__ gc, const float* __restrict__ bc,
                 float* __restrict__ h, float* __restrict__ c,
                 float* __restrict__ outs /* g_outs + t*HU, or nullptr */) {
    constexpr int NTH = 256;
    __shared__ float sz[4 * HU];
    __shared__ float scp[HU];
    __shared__ double redd[16];
    __shared__ float stat[10];

    const int b = blockIdx.x, tid = threadIdx.x;
    const float* zr = z + (size_t)b * 4 * HU;

    for (int i = tid; i < 4 * HU; i += NTH) {
        float v = zr[i];
#pragma unroll
        for (int s = 1; s < NS; ++s) v += zr[s * pstride + i];
        sz[i] = v + bias[i];
    }
    __syncthreads();

    for (int ch = 0; ch < 4; ++ch) {
        double s = 0.0, q = 0.0;
        for (int i = tid; i < HU; i += NTH) {
            double v = (double)sz[ch * HU + i];
            s += v; q += v * v;
        }
#pragma unroll
        for (int o = 16; o; o >>= 1) { s += __shfl_xor_sync(~0u, s, o); q += __shfl_xor_sync(~0u, q, o); }
        if ((tid & 31) == 0) { redd[tid >> 5] = s; redd[8 + (tid >> 5)] = q; }
        __syncthreads();
        if (tid < 32) {
            double ss = (tid < 8) ? redd[tid] : 0.0;
            double qq = (tid < 8) ? redd[8 + tid] : 0.0;
#pragma unroll
            for (int o = 4; o; o >>= 1) { ss += __shfl_xor_sync(~0u, ss, o); qq += __shfl_xor_sync(~0u, qq, o); }
            if (tid == 0) {
                double mu = ss / (double)HU;
                double var = qq / (double)HU - mu * mu;
                stat[ch] = (float)mu;
                stat[4 + ch] = (float)(1.0 / sqrt(var + 1e-5));
            }
        }
        __syncthreads();
    }

    const float mu0 = stat[0], mu1 = stat[1], mu2 = stat[2], mu3 = stat[3];
    const float r0 = stat[4], r1 = stat[5], r2 = stat[6], r3 = stat[7];

    for (int i = tid; i < HU; i += NTH) {
        float iv = (sz[i]          - mu0) * r0 * gg[i]          + bg[i];
        float jv = (sz[HU + i]     - mu1) * r1 * gg[HU + i]     + bg[HU + i];
        float fv = (sz[2 * HU + i] - mu2) * r2 * gg[2 * HU + i] + bg[2 * HU + i];
        float ov = (sz[3 * HU + i] - mu3) * r3 * gg[3 * HU + i] + bg[3 * HU + i];
        float cold = c[(size_t)b * HU + i];
        float cpre = cold * sigm(fv + 1.0f) + sigm(iv) * tanhf(jv);
        scp[i] = cpre;
        sz[3 * HU + i] = ov;
    }
    __syncthreads();

    {
        double s = 0.0, q = 0.0;
        for (int i = tid; i < HU; i += NTH) {
            double v = (double)scp[i];
            s += v; q += v * v;
        }
#pragma unroll
        for (int o = 16; o; o >>= 1) { s += __shfl_xor_sync(~0u, s, o); q += __shfl_xor_sync(~0u, q, o); }
        if ((tid & 31) == 0) { redd[tid >> 5] = s; redd[8 + (tid >> 5)] = q; }
        __syncthreads();
        if (tid < 32) {
            double ss = (tid < 8) ? redd[tid] : 0.0;
            double qq = (tid < 8) ? redd[8 + tid] : 0.0;
#pragma unroll
            for (int o = 4; o; o >>= 1) { ss += __shfl_xor_sync(~0u, ss, o); qq += __shfl_xor_sync(~0u, qq, o); }
            if (tid == 0) {
                double mu = ss / (double)HU;
                double var = qq / (double)HU - mu * mu;
                stat[8] = (float)mu;
                stat[9] = (float)(1.0 / sqrt(var + 1e-5));
            }
        }
        __syncthreads();
    }
    const float muc = stat[8], rc = stat[9];

    for (int i = tid; i < HU; i += NTH) {
        float cpre = scp[i];
        float nh = tanhf((cpre - muc) * rc * gc[i] + bc[i]) * sigm(sz[3 * HU + i]);
        float hold = h[(size_t)b * HU + i];
        float cold = c[(size_t)b * HU + i];
        float hn = 0.9f * nh + 0.1f * hold;
        float cn = 0.5f * cpre + 0.5f * cold;
        h[(size_t)b * HU + i] = hn;
        c[(size_t)b * HU + i] = cn;
        if (outs) outs[(size_t)b * T_ * HU + i] = hn;
    }
}

// ---------------- init & epilogue ----------------
__global__ void zero_states_kernel() {
    int i = blockIdx.x * blockDim.x + threadIdx.x;
    if (i < B_ * F_) { g_fh[i] = 0.f; g_fc[i] = 0.f; }
    if (i < B_ * S_) { g_sh[i] = 0.f; g_sc[i] = 0.f; }
}

__global__ void copy_states_kernel(float* __restrict__ out) {
    int i = blockIdx.x * blockDim.x + threadIdx.x;
    const int NF = B_ * F_;
    const int NS = B_ * S_;
    if (i < NF)                       out[i] = g_fh[i];
    else if (i < 2 * NF)              out[i] = g_fc[i - NF];
    else if (i < 2 * NF + NS)         out[i] = g_sh[i - 2 * NF];
    else if (i < 2 * NF + 2 * NS)     out[i] = g_sc[i - 2 * NF - NS];
}

// ---------------- launch ----------------
extern "C" void kernel_launch(void* const* d_in, const int* in_sizes, int n_in,
                              void* d_out, int out_size) {
    const float* inputs = (const float*)d_in[0];
    const float* W0  = (const float*)d_in[1];
    const float* b0  = (const float*)d_in[2];
    const float* g0  = (const float*)d_in[3];
    const float* bg0 = (const float*)d_in[4];
    const float* gc0 = (const float*)d_in[5];
    const float* bc0 = (const float*)d_in[6];
    const float* W1  = (const float*)d_in[7];
    const float* b1  = (const float*)d_in[8];
    const float* g1  = (const float*)d_in[9];
    const float* bg1 = (const float*)d_in[10];
    const float* gc1 = (const float*)d_in[11];
    const float* bc1 = (const float*)d_in[12];
    const float* WS  = (const float*)d_in[13];
    const float* bS  = (const float*)d_in[14];
    const float* gS  = (const float*)d_in[15];
    const float* bgS = (const float*)d_in[16];
    const float* gcS = (const float*)d_in[17];
    const float* bcS = (const float*)d_in[18];
    const float* Wout = (const float*)d_in[19];
    const float* bout = (const float*)d_in[20];
    float* out = (float*)d_out;

    float *fh, *fc, *sh, *sc, *z, *outs;
    cudaGetSymbolAddress((void**)&fh, g_fh);
    cudaGetSymbolAddress((void**)&fc, g_fc);
    cudaGetSymbolAddress((void**)&sh, g_sh);
    cudaGetSymbolAddress((void**)&sc, g_sc);
    cudaGetSymbolAddress((void**)&z, g_z);
    cudaGetSymbolAddress((void**)&outs, g_outs);

    const size_t psF = (size_t)B_ * 4 * F_;   // fast-cell partial plane stride
    const size_t psS = (size_t)B_ * 4 * S_;   // slow-cell partial plane stride

    zero_states_kernel<<<350, 256>>>();

    for (int t = 0; t < T_; ++t) {
        // Fast cell 0: concat(x_t[128], fh[700]) @ W0 -> 4 partial planes (R13 config)
        gemm_tf32_kernel<64, 32, 2, 2, 2, true, 4, 5><<<dim3(88, 2, 4), 128>>>(
            inputs + (size_t)t * E_, T_ * E_, E_, fh, F_, W0, nullptr, z, 4 * F_, E_ + F_, psF);
        pointwise_kernel<F_, 4><<<B_, 256>>>(z, psF, b0, g0, bg0, gc0, bc0, fh, fc, nullptr);

        // Slow cell: concat(fh[700], sh[400]) @ WS -> 7 partial planes (R13 config)
        gemm_tf32_kernel<64, 32, 2, 2, 2, true, 7, 5><<<dim3(50, 2, 7), 128>>>(
            fh, F_, F_, sh, S_, WS, nullptr, z, 4 * S_, F_ + S_, psS);
        pointwise_kernel<S_, 7><<<B_, 256>>>(z, psS, bS, gS, bgS, gcS, bcS, sh, sc, nullptr);

        // Fast cell 1: concat(sh[400], fh[700]) @ W1 -> 4 partial planes (R13 config)
        gemm_tf32_kernel<64, 32, 2, 2, 2, true, 4, 5><<<dim3(88, 2, 4), 128>>>(
            sh, S_, S_, fh, F_, W1, nullptr, z, 4 * F_, S_ + F_, psF);
        pointwise_kernel<F_, 4><<<B_, 256>>>(z, psF, b1, g1, bg1, gc1, bc1, fh, fc,
                                             outs + (size_t)t * F_);
    }

    // Output projection: NEW 64x64 2-stage pipelined tiles (was single-stage 128x128).
    // Same per-element k-accumulation order as before -> logits bit-identical.
    gemm_tf32_kernel<64, 64, 2, 2, 2, false, 1, 5><<<dim3(157, 200, 1), 128>>>(
        outs, F_, F_, outs, F_, Wout, bout, out, V_, F_, 0);

    // Final states appended after logits
    copy_states_kernel<<<1100, 256>>>(out + (size_t)B_ * T_ * V_);
}